// round 6
// baseline (speedup 1.0000x reference)
#include <cuda_runtime.h>

#define BB 2
#define LL 2048
#define HID 1024
#define NH 16
#define FDIM 16
#define HDIM 64
#define MTOT (BB*LL)   // 4096
#define BK 16

// Scratch (static __device__ — no allocation allowed)
__device__ float g_q[MTOT * NH * FDIM];   // (b*l, h*16)   4 MB
__device__ float g_k[MTOT * NH * FDIM];   // 4 MB
__device__ float g_v[MTOT * HID];         // (b*l, h*64)  16 MB
__device__ float g_o[MTOT * HID];         // 16 MB

// ---------------------------------------------------------------------------
// Core tile body: C[m,n] = sum_k A[m,k]*B[n,k], 128x128 tile, BK=16,
// double-buffered smem (one __syncthreads per K-step), register prefetch.
// 256 threads, 8x8 microtile per thread.
// ---------------------------------------------------------------------------
__device__ __forceinline__ void sgemm_tile(const float* __restrict__ A,
                                           const float* __restrict__ Bm,
                                           float* __restrict__ C,
                                           int m0, int n0, int K, int ldc) {
    __shared__ __align__(16) float As[2][BK][128];
    __shared__ __align__(16) float Bs[2][BK][128];

    const int tid  = threadIdx.x;
    const int lrow = tid >> 1;          // 0..127
    const int lcol = (tid & 1) * 8;     // 0 or 8

    const float* Ag = A  + (size_t)(m0 + lrow) * K + lcol;
    const float* Bg = Bm + (size_t)(n0 + lrow) * K + lcol;

    const int ty = tid >> 4;            // 0..15
    const int tx = tid & 15;            // 0..15

    float acc[8][8];
#pragma unroll
    for (int i = 0; i < 8; i++)
#pragma unroll
        for (int j = 0; j < 8; j++) acc[i][j] = 0.f;

    float4 a0, a1, b0, b1;

#define QK_STORE_TILE(bufi)                                                     \
    do {                                                                        \
        As[bufi][lcol + 0][lrow] = a0.x; As[bufi][lcol + 1][lrow] = a0.y;       \
        As[bufi][lcol + 2][lrow] = a0.z; As[bufi][lcol + 3][lrow] = a0.w;       \
        As[bufi][lcol + 4][lrow] = a1.x; As[bufi][lcol + 5][lrow] = a1.y;       \
        As[bufi][lcol + 6][lrow] = a1.z; As[bufi][lcol + 7][lrow] = a1.w;       \
        Bs[bufi][lcol + 0][lrow] = b0.x; Bs[bufi][lcol + 1][lrow] = b0.y;       \
        Bs[bufi][lcol + 2][lrow] = b0.z; Bs[bufi][lcol + 3][lrow] = b0.w;       \
        Bs[bufi][lcol + 4][lrow] = b1.x; Bs[bufi][lcol + 5][lrow] = b1.y;       \
        Bs[bufi][lcol + 6][lrow] = b1.z; Bs[bufi][lcol + 7][lrow] = b1.w;       \
    } while (0)

    // Prologue: tile 0 -> buffer 0
    a0 = *(const float4*)(Ag);     a1 = *(const float4*)(Ag + 4);
    b0 = *(const float4*)(Bg);     b1 = *(const float4*)(Bg + 4);
    QK_STORE_TILE(0);
    __syncthreads();

    int buf = 0;
    for (int kk = BK; kk <= K; kk += BK) {
        const bool more = (kk < K);
        if (more) {  // prefetch next tile into registers (hides gmem latency)
            a0 = *(const float4*)(Ag + kk);  a1 = *(const float4*)(Ag + kk + 4);
            b0 = *(const float4*)(Bg + kk);  b1 = *(const float4*)(Bg + kk + 4);
        }
#pragma unroll
        for (int k = 0; k < BK; k++) {
            float a[8], b[8];
            float4 ra0 = *(const float4*)&As[buf][k][ty * 8];
            float4 ra1 = *(const float4*)&As[buf][k][ty * 8 + 4];
            float4 rb0 = *(const float4*)&Bs[buf][k][tx * 8];
            float4 rb1 = *(const float4*)&Bs[buf][k][tx * 8 + 4];
            a[0]=ra0.x; a[1]=ra0.y; a[2]=ra0.z; a[3]=ra0.w;
            a[4]=ra1.x; a[5]=ra1.y; a[6]=ra1.z; a[7]=ra1.w;
            b[0]=rb0.x; b[1]=rb0.y; b[2]=rb0.z; b[3]=rb0.w;
            b[4]=rb1.x; b[5]=rb1.y; b[6]=rb1.z; b[7]=rb1.w;
#pragma unroll
            for (int i = 0; i < 8; i++)
#pragma unroll
                for (int j = 0; j < 8; j++) acc[i][j] += a[i] * b[j];
        }
        if (more) {
            QK_STORE_TILE(buf ^ 1);   // other buffer: safe, prev iter synced
            __syncthreads();
            buf ^= 1;
        }
    }
#undef QK_STORE_TILE

#pragma unroll
    for (int i = 0; i < 8; i++) {
        float* crow = C + (size_t)(m0 + ty * 8 + i) * ldc + n0 + tx * 8;
        *(float4*)(crow)     = make_float4(acc[i][0], acc[i][1], acc[i][2], acc[i][3]);
        *(float4*)(crow + 4) = make_float4(acc[i][4], acc[i][5], acc[i][6], acc[i][7]);
    }
}

// Generic N x K (both 128-multiples), ldc = N
__global__ void __launch_bounds__(256)
sgemm_nt(const float* __restrict__ A, const float* __restrict__ Bm,
         float* __restrict__ C, int K, int ldc) {
    sgemm_tile(A, Bm, C, blockIdx.y * 128, blockIdx.x * 128, K, ldc);
}

// Fused Q+K projection: one launch, 4 x-blocks (2 for Wq->q, 2 for Wk->k)
__global__ void __launch_bounds__(256)
sgemm_qk(const float* __restrict__ x,
         const float* __restrict__ Wq, const float* __restrict__ Wk,
         float* __restrict__ q, float* __restrict__ k) {
    const int bx = blockIdx.x;   // 0..3
    const float* Bm = (bx < 2) ? Wq : Wk;
    float* C        = (bx < 2) ? q  : k;
    const int n0 = (bx & 1) * 128;
    sgemm_tile(x, Bm, C, blockIdx.y * 128, n0, HID, NH * FDIM);
}

// ---------------------------------------------------------------------------
// Feature map on q and k in one launch. First nrows threads -> q (scale .25),
// next nrows -> k (scale 1).
// ---------------------------------------------------------------------------
__global__ void featmap2(float* __restrict__ q, float* __restrict__ k,
                         const float* __restrict__ gamma,
                         const float* __restrict__ beta, int nrows) {
    int i = blockIdx.x * blockDim.x + threadIdx.x;
    float scale;
    float* t;
    if (i < nrows)          { t = q; scale = 0.25f; }
    else if (i < 2 * nrows) { t = k; scale = 1.0f; i -= nrows; }
    else return;

    float* p = t + (size_t)i * 16;
    float v[16];
    float4* p4 = (float4*)p;
#pragma unroll
    for (int c = 0; c < 4; c++) {
        float4 f = p4[c];
        v[4 * c + 0] = f.x; v[4 * c + 1] = f.y; v[4 * c + 2] = f.z; v[4 * c + 3] = f.w;
    }
    float mu = 0.f;
#pragma unroll
    for (int d = 0; d < 16; d++) mu += v[d];
    mu *= (1.f / 16.f);
    float var = 0.f;
#pragma unroll
    for (int d = 0; d < 16; d++) { float dd = v[d] - mu; var += dd * dd; }
    var *= (1.f / 16.f);
    float r = rsqrtf(var + 1e-5f);
#pragma unroll
    for (int d = 0; d < 16; d++)
        v[d] = ((v[d] - mu) * r * __ldg(&gamma[d]) + __ldg(&beta[d])) * scale;
#pragma unroll
    for (int c = 0; c < 4; c++)
        p4[c] = make_float4(v[4 * c], v[4 * c + 1], v[4 * c + 2], v[4 * c + 3]);
}

// ---------------------------------------------------------------------------
// Causal quadratic "rebased" attention, v2:
//   s_ij = (q_i . k_j)^2 for j <= i;  o_i = (sum_j s_ij v_j)/(sum_j s_ij+eps)
// 256 threads/block: thread = (q-row, v-half). Each thread owns one of the
// 128 q rows of this tile and 32 of the 64 v dims. Halves the acc register
// count (64->32) vs v1 -> ~2x occupancy; dot product tree-reduced (4 partial
// chains) to cut the per-j latency chain from ~64 to ~24 cycles.
// ---------------------------------------------------------------------------
__global__ void __launch_bounds__(256)
attn(const float* __restrict__ q, const float* __restrict__ k,
     const float* __restrict__ v, float* __restrict__ o) {
    __shared__ __align__(16) float ks[128][FDIM];   // 8 KB
    __shared__ __align__(16) float vs[128][HDIM];   // 32 KB

    const int bh = blockIdx.y;
    const int b = bh >> 4;
    const int h = bh & 15;
    const int qt = gridDim.x - 1 - blockIdx.x;   // heavy blocks launch first
    const int tid = threadIdx.x;
    const int qrow = tid & 127;                  // q row within tile
    const int half = tid >> 7;                   // 0: v dims 0..31, 1: 32..63
    const int qi = qt * 128 + qrow;

    // This thread's q row in registers
    float qreg[16];
    {
        const float* qrowp = q + (size_t)(b * LL + qi) * (NH * FDIM) + h * FDIM;
#pragma unroll
        for (int c = 0; c < 4; c++) {
            float4 f = ((const float4*)qrowp)[c];
            qreg[4 * c + 0] = f.x; qreg[4 * c + 1] = f.y;
            qreg[4 * c + 2] = f.z; qreg[4 * c + 3] = f.w;
        }
    }

    float acc[32];
#pragma unroll
    for (int e = 0; e < 32; e++) acc[e] = 0.f;
    float z = 0.f;

    const int vofs = half * 32;           // this thread's 32 v dims (float idx)
    const int vofs4 = half * 8;           // in float4 units

    for (int kt = 0; kt <= qt; kt++) {
        __syncthreads();
        {
            // k tile: 512 float4 total, 2 per thread
            const int ci = tid * 2;                   // 0..510
            {
                const int row = ci >> 2, col = ci & 3;
                const float* krow = k + (size_t)(b * LL + kt * 128 + row) * (NH * FDIM) + h * FDIM;
                ((float4*)ks[row])[col]     = ((const float4*)krow)[col];
                ((float4*)ks[row])[col + 1] = ((const float4*)krow)[col + 1];
            }
            // v tile: 2048 float4 total, 8 per thread (row = tid>>1 twice? no:
            // simple: each thread loads half a v row: 8 consecutive float4)
            {
                const int row = tid >> 1;
                const int c0 = (tid & 1) * 8;
                const float* vrow = v + (size_t)(b * LL + kt * 128 + row) * HID + h * HDIM;
#pragma unroll
                for (int c = 0; c < 8; c++)
                    ((float4*)vs[row])[c0 + c] = ((const float4*)vrow)[c0 + c];
            }
        }
        __syncthreads();

        const int jmax = (kt == qt) ? qrow : 127;
#pragma unroll 2
        for (int j = 0; j <= jmax; j++) {
            // dot(q, k_j): 4 independent partial chains, tree combine
            const float4* kr = (const float4*)ks[j];
            float4 f0 = kr[0], f1 = kr[1], f2 = kr[2], f3 = kr[3];
            float s0 = qreg[0]*f0.x + qreg[1]*f0.y + qreg[2]*f0.z + qreg[3]*f0.w;
            float s1 = qreg[4]*f1.x + qreg[5]*f1.y + qreg[6]*f1.z + qreg[7]*f1.w;
            float s2 = qreg[8]*f2.x + qreg[9]*f2.y + qreg[10]*f2.z + qreg[11]*f2.w;
            float s3 = qreg[12]*f3.x + qreg[13]*f3.y + qreg[14]*f3.z + qreg[15]*f3.w;
            float s = (s0 + s1) + (s2 + s3);
            s = s * s;
            z += s;
            const float4* vr = (const float4*)vs[j] + vofs4;
#pragma unroll
            for (int c = 0; c < 8; c++) {
                float4 f = vr[c];
                acc[4 * c + 0] += s * f.x;
                acc[4 * c + 1] += s * f.y;
                acc[4 * c + 2] += s * f.z;
                acc[4 * c + 3] += s * f.w;
            }
        }
    }

    const float inv = 1.f / (z + 1e-5f);
    float* orow = o + (size_t)(b * LL + qi) * HID + h * HDIM + vofs;
#pragma unroll
    for (int c = 0; c < 8; c++)
        ((float4*)orow)[c] = make_float4(acc[4 * c + 0] * inv, acc[4 * c + 1] * inv,
                                         acc[4 * c + 2] * inv, acc[4 * c + 3] * inv);
}

// ---------------------------------------------------------------------------
extern "C" void kernel_launch(void* const* d_in, const int* in_sizes, int n_in,
                              void* d_out, int out_size) {
    const float* x     = (const float*)d_in[0];   // (2,2048,1024)
    const float* Wq    = (const float*)d_in[1];   // (256,1024)
    const float* Wk    = (const float*)d_in[2];   // (256,1024)
    const float* Wv    = (const float*)d_in[3];   // (1024,1024)
    const float* Wo    = (const float*)d_in[4];   // (1024,1024)
    const float* gamma = (const float*)d_in[5];   // (16,)
    const float* beta  = (const float*)d_in[6];   // (16,)
    float* out = (float*)d_out;

    float *q, *k, *v, *o;
    cudaGetSymbolAddress((void**)&q, g_q);
    cudaGetSymbolAddress((void**)&k, g_k);
    cudaGetSymbolAddress((void**)&v, g_v);
    cudaGetSymbolAddress((void**)&o, g_o);

    // Fused Q+K projection (one wave), then V projection
    sgemm_qk<<<dim3(4, 32), 256>>>(x, Wq, Wk, q, k);
    sgemm_nt<<<dim3(8, 32), 256>>>(x, Wv, v, HID, HID);

    // Feature maps for q (scale FD^-0.5=0.25) and k in one launch
    const int nrows = MTOT * NH;
    featmap2<<<(2 * nrows + 255) / 256, 256>>>(q, k, gamma, beta, nrows);

    // Causal quadratic attention (256 thr: 128 q-rows x 2 v-halves)
    attn<<<dim3(LL / 128, BB * NH), 256>>>(q, k, v, o);

    // Output projection
    sgemm_nt<<<dim3(8, 32), 256>>>(o, Wo, out, HID, HID);
}

// round 7
// speedup vs baseline: 1.6647x; 1.6647x over previous
#include <cuda_runtime.h>
#include <cstdint>

#define BB 2
#define LL 2048
#define HID 1024
#define NH 16
#define FDIM 16
#define HDIM 64
#define MTOT (BB*LL)   // 4096
#define BK 16

// Scratch (static __device__ — no allocation allowed)
__device__ float g_q[MTOT * NH * FDIM];   // (b*l, h*16)   4 MB
__device__ float g_k[MTOT * NH * FDIM];   // 4 MB
__device__ float g_v[MTOT * HID];         // (b*l, h*64)  16 MB
__device__ float g_o[MTOT * HID];         // 16 MB

// ---------------------------------------------------------------------------
// fp32 SGEMM (unchanged from R5 best): C[m,n] = sum_k A[m,k]*B[n,k]
// ---------------------------------------------------------------------------
__device__ __forceinline__ void sgemm_tile(const float* __restrict__ A,
                                           const float* __restrict__ Bm,
                                           float* __restrict__ C,
                                           int m0, int n0, int K, int ldc) {
    __shared__ __align__(16) float As[2][BK][128];
    __shared__ __align__(16) float Bs[2][BK][128];

    const int tid  = threadIdx.x;
    const int lrow = tid >> 1;
    const int lcol = (tid & 1) * 8;

    const float* Ag = A  + (size_t)(m0 + lrow) * K + lcol;
    const float* Bg = Bm + (size_t)(n0 + lrow) * K + lcol;

    const int ty = tid >> 4;
    const int tx = tid & 15;

    float acc[8][8];
#pragma unroll
    for (int i = 0; i < 8; i++)
#pragma unroll
        for (int j = 0; j < 8; j++) acc[i][j] = 0.f;

    float4 a0, a1, b0, b1;

#define QK_STORE_TILE(bufi)                                                     \
    do {                                                                        \
        As[bufi][lcol + 0][lrow] = a0.x; As[bufi][lcol + 1][lrow] = a0.y;       \
        As[bufi][lcol + 2][lrow] = a0.z; As[bufi][lcol + 3][lrow] = a0.w;       \
        As[bufi][lcol + 4][lrow] = a1.x; As[bufi][lcol + 5][lrow] = a1.y;       \
        As[bufi][lcol + 6][lrow] = a1.z; As[bufi][lcol + 7][lrow] = a1.w;       \
        Bs[bufi][lcol + 0][lrow] = b0.x; Bs[bufi][lcol + 1][lrow] = b0.y;       \
        Bs[bufi][lcol + 2][lrow] = b0.z; Bs[bufi][lcol + 3][lrow] = b0.w;       \
        Bs[bufi][lcol + 4][lrow] = b1.x; Bs[bufi][lcol + 5][lrow] = b1.y;       \
        Bs[bufi][lcol + 6][lrow] = b1.z; Bs[bufi][lcol + 7][lrow] = b1.w;       \
    } while (0)

    a0 = *(const float4*)(Ag);     a1 = *(const float4*)(Ag + 4);
    b0 = *(const float4*)(Bg);     b1 = *(const float4*)(Bg + 4);
    QK_STORE_TILE(0);
    __syncthreads();

    int buf = 0;
    for (int kk = BK; kk <= K; kk += BK) {
        const bool more = (kk < K);
        if (more) {
            a0 = *(const float4*)(Ag + kk);  a1 = *(const float4*)(Ag + kk + 4);
            b0 = *(const float4*)(Bg + kk);  b1 = *(const float4*)(Bg + kk + 4);
        }
#pragma unroll
        for (int k = 0; k < BK; k++) {
            float a[8], b[8];
            float4 ra0 = *(const float4*)&As[buf][k][ty * 8];
            float4 ra1 = *(const float4*)&As[buf][k][ty * 8 + 4];
            float4 rb0 = *(const float4*)&Bs[buf][k][tx * 8];
            float4 rb1 = *(const float4*)&Bs[buf][k][tx * 8 + 4];
            a[0]=ra0.x; a[1]=ra0.y; a[2]=ra0.z; a[3]=ra0.w;
            a[4]=ra1.x; a[5]=ra1.y; a[6]=ra1.z; a[7]=ra1.w;
            b[0]=rb0.x; b[1]=rb0.y; b[2]=rb0.z; b[3]=rb0.w;
            b[4]=rb1.x; b[5]=rb1.y; b[6]=rb1.z; b[7]=rb1.w;
#pragma unroll
            for (int i = 0; i < 8; i++)
#pragma unroll
                for (int j = 0; j < 8; j++) acc[i][j] += a[i] * b[j];
        }
        if (more) {
            QK_STORE_TILE(buf ^ 1);
            __syncthreads();
            buf ^= 1;
        }
    }
#undef QK_STORE_TILE

#pragma unroll
    for (int i = 0; i < 8; i++) {
        float* crow = C + (size_t)(m0 + ty * 8 + i) * ldc + n0 + tx * 8;
        *(float4*)(crow)     = make_float4(acc[i][0], acc[i][1], acc[i][2], acc[i][3]);
        *(float4*)(crow + 4) = make_float4(acc[i][4], acc[i][5], acc[i][6], acc[i][7]);
    }
}

__global__ void __launch_bounds__(256)
sgemm_nt(const float* __restrict__ A, const float* __restrict__ Bm,
         float* __restrict__ C, int K, int ldc) {
    sgemm_tile(A, Bm, C, blockIdx.y * 128, blockIdx.x * 128, K, ldc);
}

__global__ void __launch_bounds__(256)
sgemm_qk(const float* __restrict__ x,
         const float* __restrict__ Wq, const float* __restrict__ Wk,
         float* __restrict__ q, float* __restrict__ k) {
    const int bx = blockIdx.x;
    const float* Bm = (bx < 2) ? Wq : Wk;
    float* C        = (bx < 2) ? q  : k;
    const int n0 = (bx & 1) * 128;
    sgemm_tile(x, Bm, C, blockIdx.y * 128, n0, HID, NH * FDIM);
}

// ---------------------------------------------------------------------------
// Feature map on q and k in one launch (unchanged).
// ---------------------------------------------------------------------------
__global__ void featmap2(float* __restrict__ q, float* __restrict__ k,
                         const float* __restrict__ gamma,
                         const float* __restrict__ beta, int nrows) {
    int i = blockIdx.x * blockDim.x + threadIdx.x;
    float scale;
    float* t;
    if (i < nrows)          { t = q; scale = 0.25f; }
    else if (i < 2 * nrows) { t = k; scale = 1.0f; i -= nrows; }
    else return;

    float* p = t + (size_t)i * 16;
    float v[16];
    float4* p4 = (float4*)p;
#pragma unroll
    for (int c = 0; c < 4; c++) {
        float4 f = p4[c];
        v[4 * c + 0] = f.x; v[4 * c + 1] = f.y; v[4 * c + 2] = f.z; v[4 * c + 3] = f.w;
    }
    float mu = 0.f;
#pragma unroll
    for (int d = 0; d < 16; d++) mu += v[d];
    mu *= (1.f / 16.f);
    float var = 0.f;
#pragma unroll
    for (int d = 0; d < 16; d++) { float dd = v[d] - mu; var += dd * dd; }
    var *= (1.f / 16.f);
    float r = rsqrtf(var + 1e-5f);
#pragma unroll
    for (int d = 0; d < 16; d++)
        v[d] = ((v[d] - mu) * r * __ldg(&gamma[d]) + __ldg(&beta[d])) * scale;
#pragma unroll
    for (int c = 0; c < 4; c++)
        p4[c] = make_float4(v[4 * c], v[4 * c + 1], v[4 * c + 2], v[4 * c + 3]);
}

// ---------------------------------------------------------------------------
// Tensor-core causal quadratic attention (tf32 mma.sync.m16n8k8).
//   Per block: one (b,h), one 64-row q tile. 4 warps; warp w owns q rows
//   [w*16, w*16+16). Loop over 64-key tiles kt<=qt:
//     stage1: S[16,64] = Q[16,16] K[64,16]^T    (16 MMAs / warp)
//     stage2: causal mask (diag tile), s<-s^2 (fp32), z+=s, cvt tf32, STS
//     stage3: O[16,64] += S[16,64] V[64,64]     (64 MMAs / warp)
//   Epilogue: z quad-reduce (shfl), o /= (z+eps), store.
// ---------------------------------------------------------------------------
__device__ __forceinline__ void mma_tf32(float& d0, float& d1, float& d2, float& d3,
                                         uint32_t a0, uint32_t a1, uint32_t a2, uint32_t a3,
                                         uint32_t b0, uint32_t b1) {
    asm volatile("mma.sync.aligned.m16n8k8.row.col.f32.tf32.tf32.f32 "
                 "{%0,%1,%2,%3}, {%4,%5,%6,%7}, {%8,%9}, {%0,%1,%2,%3};"
                 : "+f"(d0), "+f"(d1), "+f"(d2), "+f"(d3)
                 : "r"(a0), "r"(a1), "r"(a2), "r"(a3), "r"(b0), "r"(b1));
}

__device__ __forceinline__ uint32_t f2tf(float f) {
    uint32_t u;
    asm("cvt.rna.tf32.f32 %0, %1;" : "=r"(u) : "f"(f));
    return u;
}

__global__ void __launch_bounds__(128)
attn_mma(const float* __restrict__ q, const float* __restrict__ k,
         const float* __restrict__ v, float* __restrict__ o_) {
    // tf32 bit patterns in smem; pads chosen conflict-free for the frag loads
    __shared__ uint32_t qs[64][20];       // Q tile  [qrow][fd]     5.0 KB
    __shared__ uint32_t ks[64][20];       // K tile  [key][fd]      5.0 KB
    __shared__ uint32_t vs[64][72];       // V tile  [key][hd]     18.0 KB
    __shared__ uint32_t ss[4][16][68];    // per-warp S [qrow][key] 17.0 KB

    const int bh = blockIdx.y;
    const int b = bh >> 4;
    const int h = bh & 15;
    const int qt = gridDim.x - 1 - blockIdx.x;   // heavy blocks first
    const int tid = threadIdx.x;
    const int w = tid >> 5;
    const int lane = tid & 31;
    const int g = lane >> 2;       // 0..7
    const int t = lane & 3;        // 0..3

    // ---- fill qs (once): 64 rows x 16 fd, tf32-converted
    {
        const int row = tid >> 1, c0 = (tid & 1) * 8;
        const float* src = q + (size_t)(b * LL + qt * 64 + row) * (NH * FDIM) + h * FDIM + c0;
        float4 f0 = ((const float4*)src)[0];
        float4 f1 = ((const float4*)src)[1];
        uint4 u0 = make_uint4(f2tf(f0.x), f2tf(f0.y), f2tf(f0.z), f2tf(f0.w));
        uint4 u1 = make_uint4(f2tf(f1.x), f2tf(f1.y), f2tf(f1.z), f2tf(f1.w));
        *(uint4*)&qs[row][c0]     = u0;
        *(uint4*)&qs[row][c0 + 4] = u1;
    }
    __syncthreads();

    // ---- Q fragments held in registers (A of m16n8k8, rows w*16..w*16+15)
    uint32_t qa[2][4];
#pragma unroll
    for (int kc = 0; kc < 2; kc++) {
        qa[kc][0] = qs[w * 16 + g    ][kc * 8 + t];
        qa[kc][1] = qs[w * 16 + g + 8][kc * 8 + t];
        qa[kc][2] = qs[w * 16 + g    ][kc * 8 + t + 4];
        qa[kc][3] = qs[w * 16 + g + 8][kc * 8 + t + 4];
    }

    float oc[8][4];
#pragma unroll
    for (int nt = 0; nt < 8; nt++)
#pragma unroll
        for (int r = 0; r < 4; r++) oc[nt][r] = 0.f;
    float z_lo = 0.f, z_hi = 0.f;

    for (int kt = 0; kt <= qt; kt++) {
        __syncthreads();   // previous iter's stage3 reads done before refill
        // ---- fill ks: 64 x 16
        {
            const int row = tid >> 1, c0 = (tid & 1) * 8;
            const float* src = k + (size_t)(b * LL + kt * 64 + row) * (NH * FDIM) + h * FDIM + c0;
            float4 f0 = ((const float4*)src)[0];
            float4 f1 = ((const float4*)src)[1];
            *(uint4*)&ks[row][c0]     = make_uint4(f2tf(f0.x), f2tf(f0.y), f2tf(f0.z), f2tf(f0.w));
            *(uint4*)&ks[row][c0 + 4] = make_uint4(f2tf(f1.x), f2tf(f1.y), f2tf(f1.z), f2tf(f1.w));
        }
        // ---- fill vs: 64 x 64
        {
            const int row = tid >> 1, c0 = (tid & 1) * 32;
            const float* src = v + (size_t)(b * LL + kt * 64 + row) * HID + h * HDIM + c0;
#pragma unroll
            for (int c = 0; c < 8; c++) {
                float4 f = ((const float4*)src)[c];
                *(uint4*)&vs[row][c0 + 4 * c] =
                    make_uint4(f2tf(f.x), f2tf(f.y), f2tf(f.z), f2tf(f.w));
            }
        }
        __syncthreads();

        // ---- stage 1: S = Q K^T  (C layout: rows g/g+8, cols nt*8+2t(+1))
        float sc[8][4];
#pragma unroll
        for (int nt = 0; nt < 8; nt++) {
            sc[nt][0] = sc[nt][1] = sc[nt][2] = sc[nt][3] = 0.f;
#pragma unroll
            for (int kc = 0; kc < 2; kc++) {
                uint32_t b0 = ks[nt * 8 + g][kc * 8 + t];
                uint32_t b1 = ks[nt * 8 + g][kc * 8 + t + 4];
                mma_tf32(sc[nt][0], sc[nt][1], sc[nt][2], sc[nt][3],
                         qa[kc][0], qa[kc][1], qa[kc][2], qa[kc][3], b0, b1);
            }
        }

        // ---- stage 2: causal mask (diag tile), square, z, cvt, STS
        const bool diag = (kt == qt);
        const int rlo = w * 16 + g;        // row within 64-tile
        const int rhi = rlo + 8;
#pragma unroll
        for (int nt = 0; nt < 8; nt++) {
            const int c0col = nt * 8 + 2 * t;
            float s0 = sc[nt][0], s1 = sc[nt][1], s2 = sc[nt][2], s3 = sc[nt][3];
            if (diag) {
                if (c0col     > rlo) s0 = 0.f;
                if (c0col + 1 > rlo) s1 = 0.f;
                if (c0col     > rhi) s2 = 0.f;
                if (c0col + 1 > rhi) s3 = 0.f;
            }
            s0 *= s0; s1 *= s1; s2 *= s2; s3 *= s3;
            z_lo += s0 + s1;
            z_hi += s2 + s3;
            uint2 ulo = make_uint2(f2tf(s0), f2tf(s1));
            uint2 uhi = make_uint2(f2tf(s2), f2tf(s3));
            *(uint2*)&ss[w][g    ][c0col] = ulo;
            *(uint2*)&ss[w][g + 8][c0col] = uhi;
        }
        __syncwarp();

        // ---- stage 3: O += S V
#pragma unroll
        for (int kc = 0; kc < 8; kc++) {
            uint32_t sa0 = ss[w][g    ][kc * 8 + t];
            uint32_t sa1 = ss[w][g + 8][kc * 8 + t];
            uint32_t sa2 = ss[w][g    ][kc * 8 + t + 4];
            uint32_t sa3 = ss[w][g + 8][kc * 8 + t + 4];
#pragma unroll
            for (int nt = 0; nt < 8; nt++) {
                uint32_t vb0 = vs[kc * 8 + t    ][nt * 8 + g];
                uint32_t vb1 = vs[kc * 8 + t + 4][nt * 8 + g];
                mma_tf32(oc[nt][0], oc[nt][1], oc[nt][2], oc[nt][3],
                         sa0, sa1, sa2, sa3, vb0, vb1);
            }
        }
    }

    // ---- epilogue: z reduce over the 4 lanes sharing each row (t = 0..3)
    z_lo += __shfl_xor_sync(0xffffffffu, z_lo, 1);
    z_lo += __shfl_xor_sync(0xffffffffu, z_lo, 2);
    z_hi += __shfl_xor_sync(0xffffffffu, z_hi, 1);
    z_hi += __shfl_xor_sync(0xffffffffu, z_hi, 2);
    const float inv_lo = 1.f / (z_lo + 1e-5f);
    const float inv_hi = 1.f / (z_hi + 1e-5f);

    const int qrow_lo = qt * 64 + w * 16 + g;      // global seq position
    float* obase = o_ + (size_t)(b * LL) * HID + h * HDIM;
#pragma unroll
    for (int nt = 0; nt < 8; nt++) {
        const int col = nt * 8 + 2 * t;
        *(float2*)(obase + (size_t)qrow_lo * HID + col) =
            make_float2(oc[nt][0] * inv_lo, oc[nt][1] * inv_lo);
        *(float2*)(obase + (size_t)(qrow_lo + 8) * HID + col) =
            make_float2(oc[nt][2] * inv_hi, oc[nt][3] * inv_hi);
    }
}

// ---------------------------------------------------------------------------
extern "C" void kernel_launch(void* const* d_in, const int* in_sizes, int n_in,
                              void* d_out, int out_size) {
    const float* x     = (const float*)d_in[0];   // (2,2048,1024)
    const float* Wq    = (const float*)d_in[1];   // (256,1024)
    const float* Wk    = (const float*)d_in[2];   // (256,1024)
    const float* Wv    = (const float*)d_in[3];   // (1024,1024)
    const float* Wo    = (const float*)d_in[4];   // (1024,1024)
    const float* gamma = (const float*)d_in[5];   // (16,)
    const float* beta  = (const float*)d_in[6];   // (16,)
    float* out = (float*)d_out;

    float *q, *k, *v, *o;
    cudaGetSymbolAddress((void**)&q, g_q);
    cudaGetSymbolAddress((void**)&k, g_k);
    cudaGetSymbolAddress((void**)&v, g_v);
    cudaGetSymbolAddress((void**)&o, g_o);

    // Fused Q+K projection (one wave), then V projection
    sgemm_qk<<<dim3(4, 32), 256>>>(x, Wq, Wk, q, k);
    sgemm_nt<<<dim3(8, 32), 256>>>(x, Wv, v, HID, HID);

    // Feature maps for q (scale FD^-0.5=0.25) and k in one launch
    const int nrows = MTOT * NH;
    featmap2<<<(2 * nrows + 255) / 256, 256>>>(q, k, gamma, beta, nrows);

    // Tensor-core causal quadratic attention (64-row q tiles, 4 warps)
    attn_mma<<<dim3(LL / 64, BB * NH), 128>>>(q, k, v, o);

    // Output projection
    sgemm_nt<<<dim3(8, 32), 256>>>(o, Wo, out, HID, HID);
}

// round 8
// speedup vs baseline: 2.4182x; 1.4527x over previous
#include <cuda_runtime.h>
#include <cstdint>

#define BB 2
#define LL 2048
#define HID 1024
#define NH 16
#define FDIM 16
#define HDIM 64
#define MTOT (BB*LL)   // 4096
#define BK 16

// Scratch (static __device__ — no allocation allowed)
__device__ float g_q[MTOT * NH * FDIM];   // 4 MB
__device__ float g_k[MTOT * NH * FDIM];   // 4 MB
__device__ float g_v[MTOT * HID];         // 16 MB
__device__ float g_o[MTOT * HID];         // 16 MB

// ---------------------------------------------------------------------------
// tf32 helpers (fragment layouts validated by attn_mma in R6)
// ---------------------------------------------------------------------------
__device__ __forceinline__ void mma_tf32(float& d0, float& d1, float& d2, float& d3,
                                         uint32_t a0, uint32_t a1, uint32_t a2, uint32_t a3,
                                         uint32_t b0, uint32_t b1) {
    asm volatile("mma.sync.aligned.m16n8k8.row.col.f32.tf32.tf32.f32 "
                 "{%0,%1,%2,%3}, {%4,%5,%6,%7}, {%8,%9}, {%0,%1,%2,%3};"
                 : "+f"(d0), "+f"(d1), "+f"(d2), "+f"(d3)
                 : "r"(a0), "r"(a1), "r"(a2), "r"(a3), "r"(b0), "r"(b1));
}

__device__ __forceinline__ uint32_t f2tf(float f) {
    uint32_t u;
    asm("cvt.rna.tf32.f32 %0, %1;" : "=r"(u) : "f"(f));
    return u;
}

// ---------------------------------------------------------------------------
// tf32 tensor-core GEMM: C[m,n] = sum_k A[m,k]*B[n,k]
// A: MxK row-major, B: NxK row-major. 128x128 CTA tile, 8 warps of 32x64,
// BK=16 double-buffered smem (stride-20 pad = conflict-free frag LDS).
// Used for the V and O projections (error budget: plain tf32 OK there).
// ---------------------------------------------------------------------------
__global__ void __launch_bounds__(256)
gemm_tf32_nt(const float* __restrict__ A, const float* __restrict__ Bm,
             float* __restrict__ C, int K, int N) {
    __shared__ uint32_t As[2][128][20];   // 10 KB per buf
    __shared__ uint32_t Bs[2][128][20];

    const int tid  = threadIdx.x;
    const int lrow = tid >> 1;           // 0..127
    const int lcol = (tid & 1) * 8;      // 0 or 8

    const int m0g = blockIdx.y * 128;
    const int n0g = blockIdx.x * 128;

    const float* Ag = A  + (size_t)(m0g + lrow) * K + lcol;
    const float* Bg = Bm + (size_t)(n0g + lrow) * K + lcol;

    const int w    = tid >> 5;
    const int lane = tid & 31;
    const int g = lane >> 2;             // 0..7
    const int t = lane & 3;              // 0..3
    const int wm = (w >> 1) * 32;        // warp m offset within tile
    const int wn = (w & 1) * 64;         // warp n offset within tile

    float acc[2][8][4];
#pragma unroll
    for (int mi = 0; mi < 2; mi++)
#pragma unroll
        for (int ni = 0; ni < 8; ni++)
#pragma unroll
            for (int r = 0; r < 4; r++) acc[mi][ni][r] = 0.f;

    float4 pa0, pa1, pb0, pb1;

#define GT_STORE(bufi)                                                          \
    do {                                                                        \
        *(uint4*)&As[bufi][lrow][lcol] =                                        \
            make_uint4(f2tf(pa0.x), f2tf(pa0.y), f2tf(pa0.z), f2tf(pa0.w));     \
        *(uint4*)&As[bufi][lrow][lcol + 4] =                                    \
            make_uint4(f2tf(pa1.x), f2tf(pa1.y), f2tf(pa1.z), f2tf(pa1.w));     \
        *(uint4*)&Bs[bufi][lrow][lcol] =                                        \
            make_uint4(f2tf(pb0.x), f2tf(pb0.y), f2tf(pb0.z), f2tf(pb0.w));     \
        *(uint4*)&Bs[bufi][lrow][lcol + 4] =                                    \
            make_uint4(f2tf(pb1.x), f2tf(pb1.y), f2tf(pb1.z), f2tf(pb1.w));     \
    } while (0)

    pa0 = *(const float4*)(Ag);     pa1 = *(const float4*)(Ag + 4);
    pb0 = *(const float4*)(Bg);     pb1 = *(const float4*)(Bg + 4);
    GT_STORE(0);
    __syncthreads();

    int buf = 0;
    for (int kk = BK; kk <= K; kk += BK) {
        const bool more = (kk < K);
        if (more) {
            pa0 = *(const float4*)(Ag + kk);  pa1 = *(const float4*)(Ag + kk + 4);
            pb0 = *(const float4*)(Bg + kk);  pb1 = *(const float4*)(Bg + kk + 4);
        }
#pragma unroll
        for (int kc = 0; kc < 2; kc++) {
            uint32_t ar[2][4];
#pragma unroll
            for (int mi = 0; mi < 2; mi++) {
                ar[mi][0] = As[buf][wm + mi * 16 + g    ][kc * 8 + t];
                ar[mi][1] = As[buf][wm + mi * 16 + g + 8][kc * 8 + t];
                ar[mi][2] = As[buf][wm + mi * 16 + g    ][kc * 8 + t + 4];
                ar[mi][3] = As[buf][wm + mi * 16 + g + 8][kc * 8 + t + 4];
            }
            uint32_t br[8][2];
#pragma unroll
            for (int ni = 0; ni < 8; ni++) {
                br[ni][0] = Bs[buf][wn + ni * 8 + g][kc * 8 + t];
                br[ni][1] = Bs[buf][wn + ni * 8 + g][kc * 8 + t + 4];
            }
#pragma unroll
            for (int mi = 0; mi < 2; mi++)
#pragma unroll
                for (int ni = 0; ni < 8; ni++)
                    mma_tf32(acc[mi][ni][0], acc[mi][ni][1], acc[mi][ni][2], acc[mi][ni][3],
                             ar[mi][0], ar[mi][1], ar[mi][2], ar[mi][3],
                             br[ni][0], br[ni][1]);
        }
        if (more) {
            GT_STORE(buf ^ 1);
            __syncthreads();
            buf ^= 1;
        }
    }
#undef GT_STORE

    // Epilogue: C frag layout (validated): c0=[g][2t], c1=[g][2t+1], c2/c3 = row g+8
#pragma unroll
    for (int mi = 0; mi < 2; mi++) {
        const int row_lo = m0g + wm + mi * 16 + g;
#pragma unroll
        for (int ni = 0; ni < 8; ni++) {
            const int col = n0g + wn + ni * 8 + 2 * t;
            *(float2*)(C + (size_t)row_lo * N + col) =
                make_float2(acc[mi][ni][0], acc[mi][ni][1]);
            *(float2*)(C + (size_t)(row_lo + 8) * N + col) =
                make_float2(acc[mi][ni][2], acc[mi][ni][3]);
        }
    }
}

// ---------------------------------------------------------------------------
// fp32 SGEMM (kept for Q/K projections: squaring in attention amplifies
// projection error, so these stay full precision)
// ---------------------------------------------------------------------------
__device__ __forceinline__ void sgemm_tile(const float* __restrict__ A,
                                           const float* __restrict__ Bm,
                                           float* __restrict__ C,
                                           int m0, int n0, int K, int ldc) {
    __shared__ __align__(16) float As[2][BK][128];
    __shared__ __align__(16) float Bs[2][BK][128];

    const int tid  = threadIdx.x;
    const int lrow = tid >> 1;
    const int lcol = (tid & 1) * 8;

    const float* Ag = A  + (size_t)(m0 + lrow) * K + lcol;
    const float* Bg = Bm + (size_t)(n0 + lrow) * K + lcol;

    const int ty = tid >> 4;
    const int tx = tid & 15;

    float acc[8][8];
#pragma unroll
    for (int i = 0; i < 8; i++)
#pragma unroll
        for (int j = 0; j < 8; j++) acc[i][j] = 0.f;

    float4 a0, a1, b0, b1;

#define QK_STORE_TILE(bufi)                                                     \
    do {                                                                        \
        As[bufi][lcol + 0][lrow] = a0.x; As[bufi][lcol + 1][lrow] = a0.y;       \
        As[bufi][lcol + 2][lrow] = a0.z; As[bufi][lcol + 3][lrow] = a0.w;       \
        As[bufi][lcol + 4][lrow] = a1.x; As[bufi][lcol + 5][lrow] = a1.y;       \
        As[bufi][lcol + 6][lrow] = a1.z; As[bufi][lcol + 7][lrow] = a1.w;       \
        Bs[bufi][lcol + 0][lrow] = b0.x; Bs[bufi][lcol + 1][lrow] = b0.y;       \
        Bs[bufi][lcol + 2][lrow] = b0.z; Bs[bufi][lcol + 3][lrow] = b0.w;       \
        Bs[bufi][lcol + 4][lrow] = b1.x; Bs[bufi][lcol + 5][lrow] = b1.y;       \
        Bs[bufi][lcol + 6][lrow] = b1.z; Bs[bufi][lcol + 7][lrow] = b1.w;       \
    } while (0)

    a0 = *(const float4*)(Ag);     a1 = *(const float4*)(Ag + 4);
    b0 = *(const float4*)(Bg);     b1 = *(const float4*)(Bg + 4);
    QK_STORE_TILE(0);
    __syncthreads();

    int buf = 0;
    for (int kk = BK; kk <= K; kk += BK) {
        const bool more = (kk < K);
        if (more) {
            a0 = *(const float4*)(Ag + kk);  a1 = *(const float4*)(Ag + kk + 4);
            b0 = *(const float4*)(Bg + kk);  b1 = *(const float4*)(Bg + kk + 4);
        }
#pragma unroll
        for (int k = 0; k < BK; k++) {
            float a[8], b[8];
            float4 ra0 = *(const float4*)&As[buf][k][ty * 8];
            float4 ra1 = *(const float4*)&As[buf][k][ty * 8 + 4];
            float4 rb0 = *(const float4*)&Bs[buf][k][tx * 8];
            float4 rb1 = *(const float4*)&Bs[buf][k][tx * 8 + 4];
            a[0]=ra0.x; a[1]=ra0.y; a[2]=ra0.z; a[3]=ra0.w;
            a[4]=ra1.x; a[5]=ra1.y; a[6]=ra1.z; a[7]=ra1.w;
            b[0]=rb0.x; b[1]=rb0.y; b[2]=rb0.z; b[3]=rb0.w;
            b[4]=rb1.x; b[5]=rb1.y; b[6]=rb1.z; b[7]=rb1.w;
#pragma unroll
            for (int i = 0; i < 8; i++)
#pragma unroll
                for (int j = 0; j < 8; j++) acc[i][j] += a[i] * b[j];
        }
        if (more) {
            QK_STORE_TILE(buf ^ 1);
            __syncthreads();
            buf ^= 1;
        }
    }
#undef QK_STORE_TILE

#pragma unroll
    for (int i = 0; i < 8; i++) {
        float* crow = C + (size_t)(m0 + ty * 8 + i) * ldc + n0 + tx * 8;
        *(float4*)(crow)     = make_float4(acc[i][0], acc[i][1], acc[i][2], acc[i][3]);
        *(float4*)(crow + 4) = make_float4(acc[i][4], acc[i][5], acc[i][6], acc[i][7]);
    }
}

__global__ void __launch_bounds__(256)
sgemm_qk(const float* __restrict__ x,
         const float* __restrict__ Wq, const float* __restrict__ Wk,
         float* __restrict__ q, float* __restrict__ k) {
    const int bx = blockIdx.x;
    const float* Bm = (bx < 2) ? Wq : Wk;
    float* C        = (bx < 2) ? q  : k;
    const int n0 = (bx & 1) * 128;
    sgemm_tile(x, Bm, C, blockIdx.y * 128, n0, HID, NH * FDIM);
}

// ---------------------------------------------------------------------------
// Feature map on q and k in one launch (unchanged).
// ---------------------------------------------------------------------------
__global__ void featmap2(float* __restrict__ q, float* __restrict__ k,
                         const float* __restrict__ gamma,
                         const float* __restrict__ beta, int nrows) {
    int i = blockIdx.x * blockDim.x + threadIdx.x;
    float scale;
    float* t;
    if (i < nrows)          { t = q; scale = 0.25f; }
    else if (i < 2 * nrows) { t = k; scale = 1.0f; i -= nrows; }
    else return;

    float* p = t + (size_t)i * 16;
    float v[16];
    float4* p4 = (float4*)p;
#pragma unroll
    for (int c = 0; c < 4; c++) {
        float4 f = p4[c];
        v[4 * c + 0] = f.x; v[4 * c + 1] = f.y; v[4 * c + 2] = f.z; v[4 * c + 3] = f.w;
    }
    float mu = 0.f;
#pragma unroll
    for (int d = 0; d < 16; d++) mu += v[d];
    mu *= (1.f / 16.f);
    float var = 0.f;
#pragma unroll
    for (int d = 0; d < 16; d++) { float dd = v[d] - mu; var += dd * dd; }
    var *= (1.f / 16.f);
    float r = rsqrtf(var + 1e-5f);
#pragma unroll
    for (int d = 0; d < 16; d++)
        v[d] = ((v[d] - mu) * r * __ldg(&gamma[d]) + __ldg(&beta[d])) * scale;
#pragma unroll
    for (int c = 0; c < 4; c++)
        p4[c] = make_float4(v[4 * c], v[4 * c + 1], v[4 * c + 2], v[4 * c + 3]);
}

// ---------------------------------------------------------------------------
// Tensor-core causal quadratic attention (unchanged from R6).
// ---------------------------------------------------------------------------
__global__ void __launch_bounds__(128)
attn_mma(const float* __restrict__ q, const float* __restrict__ k,
         const float* __restrict__ v, float* __restrict__ o_) {
    __shared__ uint32_t qs[64][20];
    __shared__ uint32_t ks[64][20];
    __shared__ uint32_t vs[64][72];
    __shared__ uint32_t ss[4][16][68];

    const int bh = blockIdx.y;
    const int b = bh >> 4;
    const int h = bh & 15;
    const int qt = gridDim.x - 1 - blockIdx.x;
    const int tid = threadIdx.x;
    const int w = tid >> 5;
    const int lane = tid & 31;
    const int g = lane >> 2;
    const int t = lane & 3;

    {
        const int row = tid >> 1, c0 = (tid & 1) * 8;
        const float* src = q + (size_t)(b * LL + qt * 64 + row) * (NH * FDIM) + h * FDIM + c0;
        float4 f0 = ((const float4*)src)[0];
        float4 f1 = ((const float4*)src)[1];
        *(uint4*)&qs[row][c0]     = make_uint4(f2tf(f0.x), f2tf(f0.y), f2tf(f0.z), f2tf(f0.w));
        *(uint4*)&qs[row][c0 + 4] = make_uint4(f2tf(f1.x), f2tf(f1.y), f2tf(f1.z), f2tf(f1.w));
    }
    __syncthreads();

    uint32_t qa[2][4];
#pragma unroll
    for (int kc = 0; kc < 2; kc++) {
        qa[kc][0] = qs[w * 16 + g    ][kc * 8 + t];
        qa[kc][1] = qs[w * 16 + g + 8][kc * 8 + t];
        qa[kc][2] = qs[w * 16 + g    ][kc * 8 + t + 4];
        qa[kc][3] = qs[w * 16 + g + 8][kc * 8 + t + 4];
    }

    float oc[8][4];
#pragma unroll
    for (int nt = 0; nt < 8; nt++)
#pragma unroll
        for (int r = 0; r < 4; r++) oc[nt][r] = 0.f;
    float z_lo = 0.f, z_hi = 0.f;

    for (int kt = 0; kt <= qt; kt++) {
        __syncthreads();
        {
            const int row = tid >> 1, c0 = (tid & 1) * 8;
            const float* src = k + (size_t)(b * LL + kt * 64 + row) * (NH * FDIM) + h * FDIM + c0;
            float4 f0 = ((const float4*)src)[0];
            float4 f1 = ((const float4*)src)[1];
            *(uint4*)&ks[row][c0]     = make_uint4(f2tf(f0.x), f2tf(f0.y), f2tf(f0.z), f2tf(f0.w));
            *(uint4*)&ks[row][c0 + 4] = make_uint4(f2tf(f1.x), f2tf(f1.y), f2tf(f1.z), f2tf(f1.w));
        }
        {
            const int row = tid >> 1, c0 = (tid & 1) * 32;
            const float* src = v + (size_t)(b * LL + kt * 64 + row) * HID + h * HDIM + c0;
#pragma unroll
            for (int c = 0; c < 8; c++) {
                float4 f = ((const float4*)src)[c];
                *(uint4*)&vs[row][c0 + 4 * c] =
                    make_uint4(f2tf(f.x), f2tf(f.y), f2tf(f.z), f2tf(f.w));
            }
        }
        __syncthreads();

        float sc[8][4];
#pragma unroll
        for (int nt = 0; nt < 8; nt++) {
            sc[nt][0] = sc[nt][1] = sc[nt][2] = sc[nt][3] = 0.f;
#pragma unroll
            for (int kc = 0; kc < 2; kc++) {
                uint32_t b0 = ks[nt * 8 + g][kc * 8 + t];
                uint32_t b1 = ks[nt * 8 + g][kc * 8 + t + 4];
                mma_tf32(sc[nt][0], sc[nt][1], sc[nt][2], sc[nt][3],
                         qa[kc][0], qa[kc][1], qa[kc][2], qa[kc][3], b0, b1);
            }
        }

        const bool diag = (kt == qt);
        const int rlo = w * 16 + g;
        const int rhi = rlo + 8;
#pragma unroll
        for (int nt = 0; nt < 8; nt++) {
            const int c0col = nt * 8 + 2 * t;
            float s0 = sc[nt][0], s1 = sc[nt][1], s2 = sc[nt][2], s3 = sc[nt][3];
            if (diag) {
                if (c0col     > rlo) s0 = 0.f;
                if (c0col + 1 > rlo) s1 = 0.f;
                if (c0col     > rhi) s2 = 0.f;
                if (c0col + 1 > rhi) s3 = 0.f;
            }
            s0 *= s0; s1 *= s1; s2 *= s2; s3 *= s3;
            z_lo += s0 + s1;
            z_hi += s2 + s3;
            *(uint2*)&ss[w][g    ][c0col] = make_uint2(f2tf(s0), f2tf(s1));
            *(uint2*)&ss[w][g + 8][c0col] = make_uint2(f2tf(s2), f2tf(s3));
        }
        __syncwarp();

#pragma unroll
        for (int kc = 0; kc < 8; kc++) {
            uint32_t sa0 = ss[w][g    ][kc * 8 + t];
            uint32_t sa1 = ss[w][g + 8][kc * 8 + t];
            uint32_t sa2 = ss[w][g    ][kc * 8 + t + 4];
            uint32_t sa3 = ss[w][g + 8][kc * 8 + t + 4];
#pragma unroll
            for (int nt = 0; nt < 8; nt++) {
                uint32_t vb0 = vs[kc * 8 + t    ][nt * 8 + g];
                uint32_t vb1 = vs[kc * 8 + t + 4][nt * 8 + g];
                mma_tf32(oc[nt][0], oc[nt][1], oc[nt][2], oc[nt][3],
                         sa0, sa1, sa2, sa3, vb0, vb1);
            }
        }
    }

    z_lo += __shfl_xor_sync(0xffffffffu, z_lo, 1);
    z_lo += __shfl_xor_sync(0xffffffffu, z_lo, 2);
    z_hi += __shfl_xor_sync(0xffffffffu, z_hi, 1);
    z_hi += __shfl_xor_sync(0xffffffffu, z_hi, 2);
    const float inv_lo = 1.f / (z_lo + 1e-5f);
    const float inv_hi = 1.f / (z_hi + 1e-5f);

    const int qrow_lo = qt * 64 + w * 16 + g;
    float* obase = o_ + (size_t)(b * LL) * HID + h * HDIM;
#pragma unroll
    for (int nt = 0; nt < 8; nt++) {
        const int col = nt * 8 + 2 * t;
        *(float2*)(obase + (size_t)qrow_lo * HID + col) =
            make_float2(oc[nt][0] * inv_lo, oc[nt][1] * inv_lo);
        *(float2*)(obase + (size_t)(qrow_lo + 8) * HID + col) =
            make_float2(oc[nt][2] * inv_hi, oc[nt][3] * inv_hi);
    }
}

// ---------------------------------------------------------------------------
extern "C" void kernel_launch(void* const* d_in, const int* in_sizes, int n_in,
                              void* d_out, int out_size) {
    const float* x     = (const float*)d_in[0];   // (2,2048,1024)
    const float* Wq    = (const float*)d_in[1];   // (256,1024)
    const float* Wk    = (const float*)d_in[2];   // (256,1024)
    const float* Wv    = (const float*)d_in[3];   // (1024,1024)
    const float* Wo    = (const float*)d_in[4];   // (1024,1024)
    const float* gamma = (const float*)d_in[5];   // (16,)
    const float* beta  = (const float*)d_in[6];   // (16,)
    float* out = (float*)d_out;

    float *q, *k, *v, *o;
    cudaGetSymbolAddress((void**)&q, g_q);
    cudaGetSymbolAddress((void**)&k, g_k);
    cudaGetSymbolAddress((void**)&v, g_v);
    cudaGetSymbolAddress((void**)&o, g_o);

    // Q/K projection: fp32 (precision-critical due to downstream squaring)
    sgemm_qk<<<dim3(4, 32), 256>>>(x, Wq, Wk, q, k);
    // V projection: tf32 tensor cores
    gemm_tf32_nt<<<dim3(HID / 128, MTOT / 128), 256>>>(x, Wv, v, HID, HID);

    // Feature maps for q (scale FD^-0.5=0.25) and k
    const int nrows = MTOT * NH;
    featmap2<<<(2 * nrows + 255) / 256, 256>>>(q, k, gamma, beta, nrows);

    // Tensor-core causal quadratic attention
    attn_mma<<<dim3(LL / 64, BB * NH), 128>>>(q, k, v, o);

    // Output projection: tf32 tensor cores
    gemm_tf32_nt<<<dim3(HID / 128, MTOT / 128), 256>>>(o, Wo, out, HID, HID);
}

// round 9
// speedup vs baseline: 2.9482x; 1.2192x over previous
#include <cuda_runtime.h>
#include <cstdint>

#define BB 2
#define LL 2048
#define HID 1024
#define NH 16
#define FDIM 16
#define HDIM 64
#define MTOT (BB*LL)   // 4096
#define BK 16

// Scratch (static __device__ — no allocation allowed)
__device__ float g_q[MTOT * NH * FDIM];   // 4 MB
__device__ float g_k[MTOT * NH * FDIM];   // 4 MB
__device__ float g_v[MTOT * HID];         // 16 MB
__device__ float g_o[MTOT * HID];         // 16 MB

// ---------------------------------------------------------------------------
// tf32 helpers (fragment layouts validated in R6/R7)
// ---------------------------------------------------------------------------
__device__ __forceinline__ void mma_tf32(float& d0, float& d1, float& d2, float& d3,
                                         uint32_t a0, uint32_t a1, uint32_t a2, uint32_t a3,
                                         uint32_t b0, uint32_t b1) {
    asm volatile("mma.sync.aligned.m16n8k8.row.col.f32.tf32.tf32.f32 "
                 "{%0,%1,%2,%3}, {%4,%5,%6,%7}, {%8,%9}, {%0,%1,%2,%3};"
                 : "+f"(d0), "+f"(d1), "+f"(d2), "+f"(d3)
                 : "r"(a0), "r"(a1), "r"(a2), "r"(a3), "r"(b0), "r"(b1));
}

__device__ __forceinline__ uint32_t f2tf(float f) {
    uint32_t u;
    asm("cvt.rna.tf32.f32 %0, %1;" : "=r"(u) : "f"(f));
    return u;
}

__device__ __forceinline__ uint32_t sptr(const void* p) {
    return (uint32_t)__cvta_generic_to_shared(p);
}

#define CP16(dst_s32, src_gen) \
    asm volatile("cp.async.cg.shared.global [%0], [%1], 16;" :: "r"(dst_s32), "l"(src_gen))
#define CP_COMMIT()  asm volatile("cp.async.commit_group;")
#define CP_WAIT0()   asm volatile("cp.async.wait_group 0;")

// ---------------------------------------------------------------------------
// tf32 tensor-core GEMM (unchanged from R7): C[m,n] = sum_k A[m,k]*B[n,k]
// ---------------------------------------------------------------------------
__global__ void __launch_bounds__(256)
gemm_tf32_nt(const float* __restrict__ A, const float* __restrict__ Bm,
             float* __restrict__ C, int K, int N) {
    __shared__ uint32_t As[2][128][20];
    __shared__ uint32_t Bs[2][128][20];

    const int tid  = threadIdx.x;
    const int lrow = tid >> 1;
    const int lcol = (tid & 1) * 8;

    const int m0g = blockIdx.y * 128;
    const int n0g = blockIdx.x * 128;

    const float* Ag = A  + (size_t)(m0g + lrow) * K + lcol;
    const float* Bg = Bm + (size_t)(n0g + lrow) * K + lcol;

    const int w    = tid >> 5;
    const int lane = tid & 31;
    const int g = lane >> 2;
    const int t = lane & 3;
    const int wm = (w >> 1) * 32;
    const int wn = (w & 1) * 64;

    float acc[2][8][4];
#pragma unroll
    for (int mi = 0; mi < 2; mi++)
#pragma unroll
        for (int ni = 0; ni < 8; ni++)
#pragma unroll
            for (int r = 0; r < 4; r++) acc[mi][ni][r] = 0.f;

    float4 pa0, pa1, pb0, pb1;

#define GT_STORE(bufi)                                                          \
    do {                                                                        \
        *(uint4*)&As[bufi][lrow][lcol] =                                        \
            make_uint4(f2tf(pa0.x), f2tf(pa0.y), f2tf(pa0.z), f2tf(pa0.w));     \
        *(uint4*)&As[bufi][lrow][lcol + 4] =                                    \
            make_uint4(f2tf(pa1.x), f2tf(pa1.y), f2tf(pa1.z), f2tf(pa1.w));     \
        *(uint4*)&Bs[bufi][lrow][lcol] =                                        \
            make_uint4(f2tf(pb0.x), f2tf(pb0.y), f2tf(pb0.z), f2tf(pb0.w));     \
        *(uint4*)&Bs[bufi][lrow][lcol + 4] =                                    \
            make_uint4(f2tf(pb1.x), f2tf(pb1.y), f2tf(pb1.z), f2tf(pb1.w));     \
    } while (0)

    pa0 = *(const float4*)(Ag);     pa1 = *(const float4*)(Ag + 4);
    pb0 = *(const float4*)(Bg);     pb1 = *(const float4*)(Bg + 4);
    GT_STORE(0);
    __syncthreads();

    int buf = 0;
    for (int kk = BK; kk <= K; kk += BK) {
        const bool more = (kk < K);
        if (more) {
            pa0 = *(const float4*)(Ag + kk);  pa1 = *(const float4*)(Ag + kk + 4);
            pb0 = *(const float4*)(Bg + kk);  pb1 = *(const float4*)(Bg + kk + 4);
        }
#pragma unroll
        for (int kc = 0; kc < 2; kc++) {
            uint32_t ar[2][4];
#pragma unroll
            for (int mi = 0; mi < 2; mi++) {
                ar[mi][0] = As[buf][wm + mi * 16 + g    ][kc * 8 + t];
                ar[mi][1] = As[buf][wm + mi * 16 + g + 8][kc * 8 + t];
                ar[mi][2] = As[buf][wm + mi * 16 + g    ][kc * 8 + t + 4];
                ar[mi][3] = As[buf][wm + mi * 16 + g + 8][kc * 8 + t + 4];
            }
            uint32_t br[8][2];
#pragma unroll
            for (int ni = 0; ni < 8; ni++) {
                br[ni][0] = Bs[buf][wn + ni * 8 + g][kc * 8 + t];
                br[ni][1] = Bs[buf][wn + ni * 8 + g][kc * 8 + t + 4];
            }
#pragma unroll
            for (int mi = 0; mi < 2; mi++)
#pragma unroll
                for (int ni = 0; ni < 8; ni++)
                    mma_tf32(acc[mi][ni][0], acc[mi][ni][1], acc[mi][ni][2], acc[mi][ni][3],
                             ar[mi][0], ar[mi][1], ar[mi][2], ar[mi][3],
                             br[ni][0], br[ni][1]);
        }
        if (more) {
            GT_STORE(buf ^ 1);
            __syncthreads();
            buf ^= 1;
        }
    }
#undef GT_STORE

#pragma unroll
    for (int mi = 0; mi < 2; mi++) {
        const int row_lo = m0g + wm + mi * 16 + g;
#pragma unroll
        for (int ni = 0; ni < 8; ni++) {
            const int col = n0g + wn + ni * 8 + 2 * t;
            *(float2*)(C + (size_t)row_lo * N + col) =
                make_float2(acc[mi][ni][0], acc[mi][ni][1]);
            *(float2*)(C + (size_t)(row_lo + 8) * N + col) =
                make_float2(acc[mi][ni][2], acc[mi][ni][3]);
        }
    }
}

// ---------------------------------------------------------------------------
// fp32 SGEMM for Q/K projections (precision-critical; unchanged)
// ---------------------------------------------------------------------------
__device__ __forceinline__ void sgemm_tile(const float* __restrict__ A,
                                           const float* __restrict__ Bm,
                                           float* __restrict__ C,
                                           int m0, int n0, int K, int ldc) {
    __shared__ __align__(16) float As[2][BK][128];
    __shared__ __align__(16) float Bs[2][BK][128];

    const int tid  = threadIdx.x;
    const int lrow = tid >> 1;
    const int lcol = (tid & 1) * 8;

    const float* Ag = A  + (size_t)(m0 + lrow) * K + lcol;
    const float* Bg = Bm + (size_t)(n0 + lrow) * K + lcol;

    const int ty = tid >> 4;
    const int tx = tid & 15;

    float acc[8][8];
#pragma unroll
    for (int i = 0; i < 8; i++)
#pragma unroll
        for (int j = 0; j < 8; j++) acc[i][j] = 0.f;

    float4 a0, a1, b0, b1;

#define QK_STORE_TILE(bufi)                                                     \
    do {                                                                        \
        As[bufi][lcol + 0][lrow] = a0.x; As[bufi][lcol + 1][lrow] = a0.y;       \
        As[bufi][lcol + 2][lrow] = a0.z; As[bufi][lcol + 3][lrow] = a0.w;       \
        As[bufi][lcol + 4][lrow] = a1.x; As[bufi][lcol + 5][lrow] = a1.y;       \
        As[bufi][lcol + 6][lrow] = a1.z; As[bufi][lcol + 7][lrow] = a1.w;       \
        Bs[bufi][lcol + 0][lrow] = b0.x; Bs[bufi][lcol + 1][lrow] = b0.y;       \
        Bs[bufi][lcol + 2][lrow] = b0.z; Bs[bufi][lcol + 3][lrow] = b0.w;       \
        Bs[bufi][lcol + 4][lrow] = b1.x; Bs[bufi][lcol + 5][lrow] = b1.y;       \
        Bs[bufi][lcol + 6][lrow] = b1.z; Bs[bufi][lcol + 7][lrow] = b1.w;       \
    } while (0)

    a0 = *(const float4*)(Ag);     a1 = *(const float4*)(Ag + 4);
    b0 = *(const float4*)(Bg);     b1 = *(const float4*)(Bg + 4);
    QK_STORE_TILE(0);
    __syncthreads();

    int buf = 0;
    for (int kk = BK; kk <= K; kk += BK) {
        const bool more = (kk < K);
        if (more) {
            a0 = *(const float4*)(Ag + kk);  a1 = *(const float4*)(Ag + kk + 4);
            b0 = *(const float4*)(Bg + kk);  b1 = *(const float4*)(Bg + kk + 4);
        }
#pragma unroll
        for (int k = 0; k < BK; k++) {
            float a[8], b[8];
            float4 ra0 = *(const float4*)&As[buf][k][ty * 8];
            float4 ra1 = *(const float4*)&As[buf][k][ty * 8 + 4];
            float4 rb0 = *(const float4*)&Bs[buf][k][tx * 8];
            float4 rb1 = *(const float4*)&Bs[buf][k][tx * 8 + 4];
            a[0]=ra0.x; a[1]=ra0.y; a[2]=ra0.z; a[3]=ra0.w;
            a[4]=ra1.x; a[5]=ra1.y; a[6]=ra1.z; a[7]=ra1.w;
            b[0]=rb0.x; b[1]=rb0.y; b[2]=rb0.z; b[3]=rb0.w;
            b[4]=rb1.x; b[5]=rb1.y; b[6]=rb1.z; b[7]=rb1.w;
#pragma unroll
            for (int i = 0; i < 8; i++)
#pragma unroll
                for (int j = 0; j < 8; j++) acc[i][j] += a[i] * b[j];
        }
        if (more) {
            QK_STORE_TILE(buf ^ 1);
            __syncthreads();
            buf ^= 1;
        }
    }
#undef QK_STORE_TILE

#pragma unroll
    for (int i = 0; i < 8; i++) {
        float* crow = C + (size_t)(m0 + ty * 8 + i) * ldc + n0 + tx * 8;
        *(float4*)(crow)     = make_float4(acc[i][0], acc[i][1], acc[i][2], acc[i][3]);
        *(float4*)(crow + 4) = make_float4(acc[i][4], acc[i][5], acc[i][6], acc[i][7]);
    }
}

__global__ void __launch_bounds__(256)
sgemm_qk(const float* __restrict__ x,
         const float* __restrict__ Wq, const float* __restrict__ Wk,
         float* __restrict__ q, float* __restrict__ k) {
    const int bx = blockIdx.x;
    const float* Bm = (bx < 2) ? Wq : Wk;
    float* C        = (bx < 2) ? q  : k;
    const int n0 = (bx & 1) * 128;
    sgemm_tile(x, Bm, C, blockIdx.y * 128, n0, HID, NH * FDIM);
}

// ---------------------------------------------------------------------------
// Feature map on q and k in one launch (unchanged).
// ---------------------------------------------------------------------------
__global__ void featmap2(float* __restrict__ q, float* __restrict__ k,
                         const float* __restrict__ gamma,
                         const float* __restrict__ beta, int nrows) {
    int i = blockIdx.x * blockDim.x + threadIdx.x;
    float scale;
    float* t;
    if (i < nrows)          { t = q; scale = 0.25f; }
    else if (i < 2 * nrows) { t = k; scale = 1.0f; i -= nrows; }
    else return;

    float* p = t + (size_t)i * 16;
    float v[16];
    float4* p4 = (float4*)p;
#pragma unroll
    for (int c = 0; c < 4; c++) {
        float4 f = p4[c];
        v[4 * c + 0] = f.x; v[4 * c + 1] = f.y; v[4 * c + 2] = f.z; v[4 * c + 3] = f.w;
    }
    float mu = 0.f;
#pragma unroll
    for (int d = 0; d < 16; d++) mu += v[d];
    mu *= (1.f / 16.f);
    float var = 0.f;
#pragma unroll
    for (int d = 0; d < 16; d++) { float dd = v[d] - mu; var += dd * dd; }
    var *= (1.f / 16.f);
    float r = rsqrtf(var + 1e-5f);
#pragma unroll
    for (int d = 0; d < 16; d++)
        v[d] = ((v[d] - mu) * r * __ldg(&gamma[d]) + __ldg(&beta[d])) * scale;
#pragma unroll
    for (int c = 0; c < 4; c++)
        p4[c] = make_float4(v[4 * c], v[4 * c + 1], v[4 * c + 2], v[4 * c + 3]);
}

// ---------------------------------------------------------------------------
// Tensor-core causal quadratic attention v3:
//  - cp.async prefetch of raw fp32 k/v tiles one iteration ahead (latency hidden
//    under the MMA stages); convert pass raw->tf32 smem per iteration.
//  - S relayout C-frag -> A-frag via warp shuffles (ss smem scratch removed).
//  smem pool (43 KB): [0:20KB) raw k/v staging (aliased with one-time qs),
//                     [20KB:25KB) ks tf32, [25KB:43KB) vs tf32.
// ---------------------------------------------------------------------------
__global__ void __launch_bounds__(128)
attn_mma(const float* __restrict__ q, const float* __restrict__ k,
         const float* __restrict__ v, float* __restrict__ o_) {
    __shared__ __align__(16) uint32_t pool[11008];   // 43 KB
    uint32_t* const raw_k = pool;          // [64][16] raw fp32 bits
    uint32_t* const raw_v = pool + 1024;   // [64][64] raw fp32 bits
    uint32_t* const qs    = pool;          // [64][20] (aliases staging; used once)
    uint32_t* const ks    = pool + 5120;   // [64][20] tf32
    uint32_t* const vs    = pool + 6400;   // [64][72] tf32

    const int bh = blockIdx.y;
    const int b = bh >> 4;
    const int h = bh & 15;
    const int qt = gridDim.x - 1 - blockIdx.x;   // heavy blocks first
    const int tid = threadIdx.x;
    const int lane = tid & 31;
    const int w = tid >> 5;
    const int g = lane >> 2;
    const int t = lane & 3;

    // ---- fill qs (once), extract qa frags, then release region to staging
    {
        const int row = tid >> 1, c0 = (tid & 1) * 8;
        const float* src = q + (size_t)(b * LL + qt * 64 + row) * (NH * FDIM) + h * FDIM + c0;
        float4 f0 = ((const float4*)src)[0];
        float4 f1 = ((const float4*)src)[1];
        *(uint4*)(qs + row * 20 + c0) =
            make_uint4(f2tf(f0.x), f2tf(f0.y), f2tf(f0.z), f2tf(f0.w));
        *(uint4*)(qs + row * 20 + c0 + 4) =
            make_uint4(f2tf(f1.x), f2tf(f1.y), f2tf(f1.z), f2tf(f1.w));
    }
    __syncthreads();

    uint32_t qa[2][4];
#pragma unroll
    for (int kc = 0; kc < 2; kc++) {
        qa[kc][0] = qs[(w * 16 + g    ) * 20 + kc * 8 + t];
        qa[kc][1] = qs[(w * 16 + g + 8) * 20 + kc * 8 + t];
        qa[kc][2] = qs[(w * 16 + g    ) * 20 + kc * 8 + t + 4];
        qa[kc][3] = qs[(w * 16 + g + 8) * 20 + kc * 8 + t + 4];
    }
    __syncthreads();   // all reads of qs done -> staging region free

    const float* kbase = k + (size_t)(b * LL) * (NH * FDIM) + h * FDIM;  // row stride 256
    const float* vbase = v + (size_t)(b * LL) * HID + h * HDIM;          // row stride 1024

    // cp.async one 64-key tile (k: 256 chunks of 16B, v: 1024 chunks of 16B)
    auto issue_tile = [&](int kt) {
        const float* kb = kbase + (size_t)(kt * 64) * (NH * FDIM);
        const float* vb = vbase + (size_t)(kt * 64) * HID;
#pragma unroll
        for (int i = 0; i < 2; i++) {
            const int c = tid + 128 * i;
            const int row = c >> 2, quad = c & 3;
            CP16(sptr(raw_k + row * 16 + quad * 4), kb + row * 256 + quad * 4);
        }
#pragma unroll
        for (int i = 0; i < 8; i++) {
            const int c = tid + 128 * i;
            const int row = c >> 4, quad = c & 15;
            CP16(sptr(raw_v + row * 64 + quad * 4), vb + row * 1024 + quad * 4);
        }
        CP_COMMIT();
    };

    issue_tile(0);

    float oc[8][4];
#pragma unroll
    for (int nt = 0; nt < 8; nt++)
#pragma unroll
        for (int r = 0; r < 4; r++) oc[nt][r] = 0.f;
    float z_lo = 0.f, z_hi = 0.f;

    const int src1 = (lane & ~3) | (t >> 1);
    const int src2 = src1 | 2;

    for (int kt = 0; kt <= qt; kt++) {
        CP_WAIT0();
        __syncthreads();   // staging(kt) visible to all; ks/vs free (prev MMAs done)

        // ---- convert raw fp32 -> tf32 padded tiles
#pragma unroll
        for (int i = 0; i < 2; i++) {
            const int c = tid + 128 * i;
            const int row = c >> 2, quad = c & 3;
            float4 f = *(const float4*)(raw_k + row * 16 + quad * 4);
            *(uint4*)(ks + row * 20 + quad * 4) =
                make_uint4(f2tf(f.x), f2tf(f.y), f2tf(f.z), f2tf(f.w));
        }
#pragma unroll
        for (int i = 0; i < 8; i++) {
            const int c = tid + 128 * i;
            const int row = c >> 4, quad = c & 15;
            float4 f = *(const float4*)(raw_v + row * 64 + quad * 4);
            *(uint4*)(vs + row * 72 + quad * 4) =
                make_uint4(f2tf(f.x), f2tf(f.y), f2tf(f.z), f2tf(f.w));
        }
        __syncthreads();   // convert done: staging free, tf32 tiles ready

        if (kt < qt) issue_tile(kt + 1);   // overlaps with MMA stages below

        // ---- stage 1: S = Q K^T
        float sc[8][4];
#pragma unroll
        for (int nt = 0; nt < 8; nt++) {
            sc[nt][0] = sc[nt][1] = sc[nt][2] = sc[nt][3] = 0.f;
#pragma unroll
            for (int kc = 0; kc < 2; kc++) {
                uint32_t b0 = ks[(nt * 8 + g) * 20 + kc * 8 + t];
                uint32_t b1 = ks[(nt * 8 + g) * 20 + kc * 8 + t + 4];
                mma_tf32(sc[nt][0], sc[nt][1], sc[nt][2], sc[nt][3],
                         qa[kc][0], qa[kc][1], qa[kc][2], qa[kc][3], b0, b1);
            }
        }

        // ---- stage 2: causal mask (diag tile), square, z accum, cvt to tf32
        const bool diag = (kt == qt);
        const int rlo = w * 16 + g;
        const int rhi = rlo + 8;
        uint32_t scq[8][4];
#pragma unroll
        for (int nt = 0; nt < 8; nt++) {
            const int c0col = nt * 8 + 2 * t;
            float s0 = sc[nt][0], s1 = sc[nt][1], s2 = sc[nt][2], s3 = sc[nt][3];
            if (diag) {
                if (c0col     > rlo) s0 = 0.f;
                if (c0col + 1 > rlo) s1 = 0.f;
                if (c0col     > rhi) s2 = 0.f;
                if (c0col + 1 > rhi) s3 = 0.f;
            }
            s0 *= s0; s1 *= s1; s2 *= s2; s3 *= s3;
            z_lo += s0 + s1;
            z_hi += s2 + s3;
            scq[nt][0] = f2tf(s0); scq[nt][1] = f2tf(s1);
            scq[nt][2] = f2tf(s2); scq[nt][3] = f2tf(s3);
        }

        // ---- stage 3: O += S V, S relayout via shuffles (C-frag -> A-frag)
#pragma unroll
        for (int kc = 0; kc < 8; kc++) {
            uint32_t u0 = __shfl_sync(0xffffffffu, scq[kc][0], src1);
            uint32_t u1 = __shfl_sync(0xffffffffu, scq[kc][1], src1);
            uint32_t u2 = __shfl_sync(0xffffffffu, scq[kc][2], src1);
            uint32_t u3 = __shfl_sync(0xffffffffu, scq[kc][3], src1);
            uint32_t w0 = __shfl_sync(0xffffffffu, scq[kc][0], src2);
            uint32_t w1 = __shfl_sync(0xffffffffu, scq[kc][1], src2);
            uint32_t w2 = __shfl_sync(0xffffffffu, scq[kc][2], src2);
            uint32_t w3 = __shfl_sync(0xffffffffu, scq[kc][3], src2);
            const bool odd = (t & 1);
            const uint32_t sa0 = odd ? u1 : u0;
            const uint32_t sa1 = odd ? u3 : u2;
            const uint32_t sa2 = odd ? w1 : w0;
            const uint32_t sa3 = odd ? w3 : w2;
#pragma unroll
            for (int nt = 0; nt < 8; nt++) {
                uint32_t vb0 = vs[(kc * 8 + t    ) * 72 + nt * 8 + g];
                uint32_t vb1 = vs[(kc * 8 + t + 4) * 72 + nt * 8 + g];
                mma_tf32(oc[nt][0], oc[nt][1], oc[nt][2], oc[nt][3],
                         sa0, sa1, sa2, sa3, vb0, vb1);
            }
        }
    }

    // ---- epilogue: z reduce over the 4 lanes of each row quad, normalize, store
    z_lo += __shfl_xor_sync(0xffffffffu, z_lo, 1);
    z_lo += __shfl_xor_sync(0xffffffffu, z_lo, 2);
    z_hi += __shfl_xor_sync(0xffffffffu, z_hi, 1);
    z_hi += __shfl_xor_sync(0xffffffffu, z_hi, 2);
    const float inv_lo = 1.f / (z_lo + 1e-5f);
    const float inv_hi = 1.f / (z_hi + 1e-5f);

    const int qrow_lo = qt * 64 + w * 16 + g;
    float* obase = o_ + (size_t)(b * LL) * HID + h * HDIM;
#pragma unroll
    for (int nt = 0; nt < 8; nt++) {
        const int col = nt * 8 + 2 * t;
        *(float2*)(obase + (size_t)qrow_lo * HID + col) =
            make_float2(oc[nt][0] * inv_lo, oc[nt][1] * inv_lo);
        *(float2*)(obase + (size_t)(qrow_lo + 8) * HID + col) =
            make_float2(oc[nt][2] * inv_hi, oc[nt][3] * inv_hi);
    }
}

// ---------------------------------------------------------------------------
extern "C" void kernel_launch(void* const* d_in, const int* in_sizes, int n_in,
                              void* d_out, int out_size) {
    const float* x     = (const float*)d_in[0];   // (2,2048,1024)
    const float* Wq    = (const float*)d_in[1];   // (256,1024)
    const float* Wk    = (const float*)d_in[2];   // (256,1024)
    const float* Wv    = (const float*)d_in[3];   // (1024,1024)
    const float* Wo    = (const float*)d_in[4];   // (1024,1024)
    const float* gamma = (const float*)d_in[5];   // (16,)
    const float* beta  = (const float*)d_in[6];   // (16,)
    float* out = (float*)d_out;

    float *q, *k, *v, *o;
    cudaGetSymbolAddress((void**)&q, g_q);
    cudaGetSymbolAddress((void**)&k, g_k);
    cudaGetSymbolAddress((void**)&v, g_v);
    cudaGetSymbolAddress((void**)&o, g_o);

    // Q/K projection: fp32 (precision-critical due to downstream squaring)
    sgemm_qk<<<dim3(4, 32), 256>>>(x, Wq, Wk, q, k);
    // V projection: tf32 tensor cores
    gemm_tf32_nt<<<dim3(HID / 128, MTOT / 128), 256>>>(x, Wv, v, HID, HID);

    // Feature maps for q (scale FD^-0.5=0.25) and k
    const int nrows = MTOT * NH;
    featmap2<<<(2 * nrows + 255) / 256, 256>>>(q, k, gamma, beta, nrows);

    // Tensor-core causal quadratic attention (pipelined, shfl relayout)
    attn_mma<<<dim3(LL / 64, BB * NH), 128>>>(q, k, v, o);

    // Output projection: tf32 tensor cores
    gemm_tf32_nt<<<dim3(HID / 128, MTOT / 128), 256>>>(o, Wo, out, HID, HID);
}